// round 11
// baseline (speedup 1.0000x reference)
#include <cuda_runtime.h>

#define NN 50000
#define EE 800000
#define ET 850000   // EE + NN self loops
#define HID 96
#define NEG 0.2f

#define SCAN_TPB 256
#define SCAN_BLOCKS ((NN + SCAN_TPB - 1) / SCAN_TPB)   // 196

// ---------------- scratch (no cudaMalloc allowed) ----------------
__device__ float g_h[NN * HID];
__device__ float g_bufA[NN * HID];
__device__ float g_bufB[NN * HID];
__device__ float g_es[NN];
__device__ float g_ed[NN];
__device__ float g_hf[NN];
__device__ float g_esf[NN];
__device__ float g_edf[NN];
__device__ int   g_cnt[NN];
__device__ int   g_rowptr[NN + 1];
__device__ int   g_fill[NN];
__device__ int   g_srcbuf[ET];
__device__ int   g_bsum[SCAN_BLOCKS];
__device__ int   g_is64;

__device__ __forceinline__ float* sel_buf(int s) {
    return (s == 1) ? g_bufA : g_bufB;
}

// ---------------- init: zero counters + dtype probe ----------------
// edge_index dtype: reference asks int64 but JAX without x64 emits int32.
__global__ void init_kernel(const int* __restrict__ ei32) {
    int i = blockIdx.x * blockDim.x + threadIdx.x;
    if (i < NN) g_cnt[i] = 0;
    if (blockIdx.x == 0) {
        __shared__ int nz;
        if (threadIdx.x == 0) nz = 0;
        __syncthreads();
        if (ei32[2 * threadIdx.x + 1] != 0) nz = 1;  // benign race
        __syncthreads();
        if (threadIdx.x == 0) g_is64 = (nz == 0) ? 1 : 0;
    }
}

__device__ __forceinline__ int load_idx(const void* ei, long long pos) {
    if (g_is64) return (int)((const long long*)ei)[pos];
    return ((const int*)ei)[pos];
}

// ---------------- CSR build ----------------
__global__ void hist_kernel(const void* __restrict__ ei) {
    int j = blockIdx.x * blockDim.x + threadIdx.x;
    if (j >= ET) return;
    int dst = (j < EE) ? load_idx(ei, (long long)EE + j) : (j - EE);
    atomicAdd(&g_cnt[dst], 1);
}

__global__ void bsum_kernel() {
    __shared__ int sh[SCAN_TPB];
    int t = threadIdx.x;
    int i = blockIdx.x * SCAN_TPB + t;
    sh[t] = (i < NN) ? g_cnt[i] : 0;
    __syncthreads();
#pragma unroll
    for (int off = SCAN_TPB / 2; off > 0; off >>= 1) {
        if (t < off) sh[t] += sh[t + off];
        __syncthreads();
    }
    if (t == 0) g_bsum[blockIdx.x] = sh[0];
}

__global__ void scanout_kernel() {
    __shared__ int shoff[SCAN_TPB];
    __shared__ int sh[SCAN_TPB];
    int t = threadIdx.x;
    shoff[t] = (t < blockIdx.x && t < SCAN_BLOCKS) ? g_bsum[t] : 0;
    int i = blockIdx.x * SCAN_TPB + t;
    int c = (i < NN) ? g_cnt[i] : 0;
    sh[t] = c;
    __syncthreads();
#pragma unroll
    for (int off = SCAN_TPB / 2; off > 0; off >>= 1) {
        if (t < off) shoff[t] += shoff[t + off];
        __syncthreads();
    }
#pragma unroll
    for (int off = 1; off < SCAN_TPB; off <<= 1) {
        int v = sh[t];
        int add = (t >= off) ? sh[t - off] : 0;
        __syncthreads();
        sh[t] = v + add;
        __syncthreads();
    }
    int excl = sh[t] - c + shoff[0];
    if (i < NN) {
        g_rowptr[i] = excl;
        g_fill[i]   = excl;
    }
    if (i == NN - 1) g_rowptr[NN] = ET;
}

__global__ void scatter_kernel(const void* __restrict__ ei) {
    int j = blockIdx.x * blockDim.x + threadIdx.x;
    if (j >= ET) return;
    int src, dst;
    if (j < EE) {
        src = load_idx(ei, j);
        dst = load_idx(ei, (long long)EE + j);
    } else {
        src = dst = j - EE;
    }
    int pos = atomicAdd(&g_fill[dst], 1);
    g_srcbuf[pos] = src;
}

// ---------------- GEMM: g_h = in @ W  (8 nodes/block, 96 threads, f32x2) ----------------
template <int IN>
__global__ void gemm_kernel(const float* __restrict__ x, int in_sel,
                            const float* __restrict__ W) {
    __shared__ __align__(16) float2 xs[IN][4];   // [k][pair]; pair p = nodes (2p, 2p+1)
    const float* in = (in_sel == 0) ? x : sel_buf(in_sel);
    int nb = blockIdx.x * 8;
    int o  = threadIdx.x;   // 0..95
    for (int idx = o; idx < 8 * IN; idx += HID) {
        int n = idx / IN, c = idx % IN;
        ((float*)&xs[c][n >> 1])[n & 1] = in[(nb + n) * IN + c];
    }
    __syncthreads();

    unsigned long long acc0 = 0ull, acc1 = 0ull, acc2 = 0ull, acc3 = 0ull;
#pragma unroll 8
    for (int k = 0; k < IN; k++) {
        float w = W[k * HID + o];
        unsigned long long ww;
        asm("mov.b64 %0, {%1, %1};" : "=l"(ww) : "r"(__float_as_uint(w)));
        ulonglong2 X01 = *reinterpret_cast<const ulonglong2*>(&xs[k][0]);
        ulonglong2 X23 = *reinterpret_cast<const ulonglong2*>(&xs[k][2]);
        asm("fma.rn.f32x2 %0, %1, %2, %0;" : "+l"(acc0) : "l"(X01.x), "l"(ww));
        asm("fma.rn.f32x2 %0, %1, %2, %0;" : "+l"(acc1) : "l"(X01.y), "l"(ww));
        asm("fma.rn.f32x2 %0, %1, %2, %0;" : "+l"(acc2) : "l"(X23.x), "l"(ww));
        asm("fma.rn.f32x2 %0, %1, %2, %0;" : "+l"(acc3) : "l"(X23.y), "l"(ww));
    }

    g_h[(nb + 0) * HID + o] = __uint_as_float((unsigned)acc0);
    g_h[(nb + 1) * HID + o] = __uint_as_float((unsigned)(acc0 >> 32));
    g_h[(nb + 2) * HID + o] = __uint_as_float((unsigned)acc1);
    g_h[(nb + 3) * HID + o] = __uint_as_float((unsigned)(acc1 >> 32));
    g_h[(nb + 4) * HID + o] = __uint_as_float((unsigned)acc2);
    g_h[(nb + 5) * HID + o] = __uint_as_float((unsigned)(acc2 >> 32));
    g_h[(nb + 6) * HID + o] = __uint_as_float((unsigned)acc3);
    g_h[(nb + 7) * HID + o] = __uint_as_float((unsigned)(acc3 >> 32));
}

// ---------------- per-node attention logits: es = h.a_s, ed = h.a_d ----------------
__global__ void esed_kernel(const float* __restrict__ as, const float* __restrict__ ad) {
    int node = (blockIdx.x * blockDim.x + threadIdx.x) >> 5;
    int lane = threadIdx.x & 31;
    if (node >= NN) return;
    float vs = 0.f, vd = 0.f;
    if (lane < 24) {
        float4 hv = ((const float4*)(g_h + node * HID))[lane];
        float4 a4 = ((const float4*)as)[lane];
        float4 d4 = ((const float4*)ad)[lane];
        vs = hv.x * a4.x + hv.y * a4.y + hv.z * a4.z + hv.w * a4.w;
        vd = hv.x * d4.x + hv.y * d4.y + hv.z * d4.z + hv.w * d4.w;
    }
#pragma unroll
    for (int off = 16; off; off >>= 1) {
        vs += __shfl_xor_sync(0xFFFFFFFFu, vs, off);
        vd += __shfl_xor_sync(0xFFFFFFFFu, vd, off);
    }
    if (lane == 0) { g_es[node] = vs; g_ed[node] = vd; }
}

// ---------------- aggregation: one warp per destination node ----------------
// Pass A: lane-parallel segment max (lanes split edges).
// Pass B: serial per-edge broadcast loop; ONE LDG.128 fp32 h gather on lanes
// 0-23 (lane l -> cols 4l..4l+3). 3 LDG issues/edge instead of 5.
template <bool RESID, bool FINAL>
__global__ void agg_kernel(const float* __restrict__ b, int resid_sel, int out_sel,
                           const float* __restrict__ Wf,
                           const float* __restrict__ asf,
                           const float* __restrict__ adf) {
    int node = (blockIdx.x * blockDim.x + threadIdx.x) >> 5;
    int lane = threadIdx.x & 31;
    if (node >= NN) return;
    int beg = g_rowptr[node], end = g_rowptr[node + 1];
    float edst = g_ed[node];
    bool act = lane < 24;

    float m = -1e30f;
    for (int j = beg + lane; j < end; j += 32) {
        float e = g_es[g_srcbuf[j]] + edst;
        e = (e > 0.f) ? e : NEG * e;
        m = fmaxf(m, e);
    }
#pragma unroll
    for (int off = 16; off; off >>= 1)
        m = fmaxf(m, __shfl_xor_sync(0xFFFFFFFFu, m, off));

    float a0 = 0.f, a1 = 0.f, a2 = 0.f, a3 = 0.f, ssum = 0.f;
#pragma unroll 4
    for (int j = beg; j < end; j++) {
        int s = g_srcbuf[j];                 // broadcast load
        float e = g_es[s] + edst;            // broadcast load
        e = (e > 0.f) ? e : NEG * e;
        float ex = __expf(e - m);
        ssum += ex;
        if (act) {
            float4 hv = *(const float4*)(g_h + s * HID + lane * 4);
            a0 += ex * hv.x; a1 += ex * hv.y;
            a2 += ex * hv.z; a3 += ex * hv.w;
        }
    }
    float inv = 1.f / ssum;
    if (FINAL) {
        float v = 0.f;
        if (act) {
            float4 b4 = ((const float4*)b)[lane];
            float o0 = a0 * inv + b4.x, o1 = a1 * inv + b4.y;
            float o2 = a2 * inv + b4.z, o3 = a3 * inv + b4.w;
            if (RESID) {
                float4 r4 = ((const float4*)(sel_buf(resid_sel) + node * HID))[lane];
                o0 += r4.x; o1 += r4.y; o2 += r4.z; o3 += r4.w;
            }
            o0 = fmaxf(o0, 0.f); o1 = fmaxf(o1, 0.f);
            o2 = fmaxf(o2, 0.f); o3 = fmaxf(o3, 0.f);
            float4 w4 = ((const float4*)Wf)[lane];
            v = o0 * w4.x + o1 * w4.y + o2 * w4.z + o3 * w4.w;
        }
#pragma unroll
        for (int off = 16; off; off >>= 1)
            v += __shfl_xor_sync(0xFFFFFFFFu, v, off);
        if (lane == 0) {
            g_hf[node]  = v;
            g_esf[node] = v * asf[0];
            g_edf[node] = v * adf[0];
        }
    } else if (act) {
        float4 b4 = ((const float4*)b)[lane];
        float o0 = a0 * inv + b4.x, o1 = a1 * inv + b4.y;
        float o2 = a2 * inv + b4.z, o3 = a3 * inv + b4.w;
        if (RESID) {
            float4 r4 = ((const float4*)(sel_buf(resid_sel) + node * HID))[lane];
            o0 += r4.x; o1 += r4.y; o2 += r4.z; o3 += r4.w;
        }
        o0 = fmaxf(o0, 0.f); o1 = fmaxf(o1, 0.f);
        o2 = fmaxf(o2, 0.f); o3 = fmaxf(o3, 0.f);
        ((float4*)(sel_buf(out_sel) + node * HID))[lane] = make_float4(o0, o1, o2, o3);
    }
}

// ---------------- final aggregation (out dim = 1) ----------------
__global__ void fagg_kernel(const float* __restrict__ bf, float* __restrict__ out) {
    int node = (blockIdx.x * blockDim.x + threadIdx.x) >> 5;
    int lane = threadIdx.x & 31;
    if (node >= NN) return;
    int beg = g_rowptr[node], end = g_rowptr[node + 1];
    float edst = g_edf[node];

    float m = -1e30f;
    for (int j = beg + lane; j < end; j += 32) {
        float e = g_esf[g_srcbuf[j]] + edst;
        e = (e > 0.f) ? e : NEG * e;
        m = fmaxf(m, e);
    }
#pragma unroll
    for (int off = 16; off; off >>= 1)
        m = fmaxf(m, __shfl_xor_sync(0xFFFFFFFFu, m, off));

    float ssum = 0.f, wsum = 0.f;
    for (int j = beg + lane; j < end; j += 32) {
        int s = g_srcbuf[j];
        float e = g_esf[s] + edst;
        e = (e > 0.f) ? e : NEG * e;
        float ex = __expf(e - m);
        ssum += ex;
        wsum += ex * g_hf[s];
    }
#pragma unroll
    for (int off = 16; off; off >>= 1) {
        ssum += __shfl_xor_sync(0xFFFFFFFFu, ssum, off);
        wsum += __shfl_xor_sync(0xFFFFFFFFu, wsum, off);
    }
    if (lane == 0) out[node] = wsum / ssum + bf[0];
}

// ---------------- launch ----------------
extern "C" void kernel_launch(void* const* d_in, const int* in_sizes, int n_in,
                              void* d_out, int out_size) {
    const float* x   = (const float*)d_in[0];
    const void*  ei  = d_in[1];
    const float* W0  = (const float*)d_in[3];
    const float* as0 = (const float*)d_in[4];
    const float* ad0 = (const float*)d_in[5];
    const float* b0  = (const float*)d_in[6];
    const float* W1  = (const float*)d_in[7];
    const float* as1 = (const float*)d_in[8];
    const float* ad1 = (const float*)d_in[9];
    const float* b1  = (const float*)d_in[10];
    const float* W2  = (const float*)d_in[11];
    const float* as2 = (const float*)d_in[12];
    const float* ad2 = (const float*)d_in[13];
    const float* b2  = (const float*)d_in[14];
    const float* Wf  = (const float*)d_in[15];
    const float* asf = (const float*)d_in[16];
    const float* adf = (const float*)d_in[17];
    const float* bf  = (const float*)d_in[18];
    float* out = (float*)d_out;

    const int TPB = 256;
    const int edge_blocks = (ET + TPB - 1) / TPB;
    const int node_warp_blocks = (NN * 32 + TPB - 1) / TPB;   // 1 warp per node

    // CSR build (sort edges by dst, include self loops)
    init_kernel<<<SCAN_BLOCKS, SCAN_TPB>>>((const int*)ei);
    hist_kernel<<<edge_blocks, TPB>>>(ei);
    bsum_kernel<<<SCAN_BLOCKS, SCAN_TPB>>>();
    scanout_kernel<<<SCAN_BLOCKS, SCAN_TPB>>>();
    scatter_kernel<<<edge_blocks, TPB>>>(ei);

    // Layer 0: 32 -> 96, no residual, relu.  out -> bufA
    gemm_kernel<32><<<NN / 8, HID>>>(x, 0, W0);
    esed_kernel<<<node_warp_blocks, TPB>>>(as0, ad0);
    agg_kernel<false, false><<<node_warp_blocks, TPB>>>(b0, 0, 1, nullptr, nullptr, nullptr);

    // Layer 1: 96 -> 96, residual(bufA), relu.  out -> bufB
    gemm_kernel<HID><<<NN / 8, HID>>>(nullptr, 1, W1);
    esed_kernel<<<node_warp_blocks, TPB>>>(as1, ad1);
    agg_kernel<true, false><<<node_warp_blocks, TPB>>>(b1, 1, 2, nullptr, nullptr, nullptr);

    // Layer 2: 96 -> 96, residual(bufB), relu, fused final 96->1 projection
    gemm_kernel<HID><<<NN / 8, HID>>>(nullptr, 2, W2);
    esed_kernel<<<node_warp_blocks, TPB>>>(as2, ad2);
    agg_kernel<true, true><<<node_warp_blocks, TPB>>>(b2, 2, 0, Wf, asf, adf);

    // Final layer aggregation (dim 1)
    fagg_kernel<<<node_warp_blocks, TPB>>>(bf, out);
}

// round 12
// speedup vs baseline: 1.0479x; 1.0479x over previous
#include <cuda_runtime.h>

#define NN 50000
#define EE 800000
#define ET 850000   // EE + NN self loops
#define HID 96
#define NEG 0.2f

#define SCAN_TPB 256
#define SCAN_BLOCKS ((NN + SCAN_TPB - 1) / SCAN_TPB)   // 196

// ---------------- scratch (no cudaMalloc allowed) ----------------
__device__ float g_h[NN * HID];
__device__ float g_bufA[NN * HID];
__device__ float g_bufB[NN * HID];
__device__ float g_es[NN];
__device__ float g_ed[NN];
__device__ float g_hf[NN];
__device__ float g_esf[NN];
__device__ float g_edf[NN];
__device__ unsigned g_esmax_u;      // ordered-float encoded global max of es
__device__ int   g_cnt[NN];
__device__ int   g_rowptr[NN + 1];
__device__ int   g_fill[NN];
__device__ int   g_srcbuf[ET];
__device__ int   g_bsum[SCAN_BLOCKS];
__device__ int   g_is64;

__device__ __forceinline__ float* sel_buf(int s) {
    return (s == 1) ? g_bufA : g_bufB;
}

// order-preserving float <-> uint encoding (for atomicMax on floats)
__device__ __forceinline__ unsigned fenc(float f) {
    unsigned u = __float_as_uint(f);
    return (u & 0x80000000u) ? ~u : (u | 0x80000000u);
}
__device__ __forceinline__ float fdec(unsigned e) {
    unsigned u = (e & 0x80000000u) ? (e & 0x7FFFFFFFu) : ~e;
    return __uint_as_float(u);
}

// ---------------- init: zero counters + dtype probe ----------------
// edge_index dtype: reference asks int64 but JAX without x64 emits int32.
__global__ void init_kernel(const int* __restrict__ ei32) {
    int i = blockIdx.x * blockDim.x + threadIdx.x;
    if (i < NN) g_cnt[i] = 0;
    if (blockIdx.x == 0) {
        __shared__ int nz;
        if (threadIdx.x == 0) nz = 0;
        __syncthreads();
        if (ei32[2 * threadIdx.x + 1] != 0) nz = 1;  // benign race
        __syncthreads();
        if (threadIdx.x == 0) g_is64 = (nz == 0) ? 1 : 0;
    }
}

__device__ __forceinline__ int load_idx(const void* ei, long long pos) {
    if (g_is64) return (int)((const long long*)ei)[pos];
    return ((const int*)ei)[pos];
}

// ---------------- CSR build ----------------
__global__ void hist_kernel(const void* __restrict__ ei) {
    int j = blockIdx.x * blockDim.x + threadIdx.x;
    if (j >= ET) return;
    int dst = (j < EE) ? load_idx(ei, (long long)EE + j) : (j - EE);
    atomicAdd(&g_cnt[dst], 1);
}

__global__ void bsum_kernel() {
    __shared__ int sh[SCAN_TPB];
    int t = threadIdx.x;
    int i = blockIdx.x * SCAN_TPB + t;
    sh[t] = (i < NN) ? g_cnt[i] : 0;
    __syncthreads();
#pragma unroll
    for (int off = SCAN_TPB / 2; off > 0; off >>= 1) {
        if (t < off) sh[t] += sh[t + off];
        __syncthreads();
    }
    if (t == 0) g_bsum[blockIdx.x] = sh[0];
}

__global__ void scanout_kernel() {
    __shared__ int shoff[SCAN_TPB];
    __shared__ int sh[SCAN_TPB];
    int t = threadIdx.x;
    shoff[t] = (t < blockIdx.x && t < SCAN_BLOCKS) ? g_bsum[t] : 0;
    int i = blockIdx.x * SCAN_TPB + t;
    int c = (i < NN) ? g_cnt[i] : 0;
    sh[t] = c;
    __syncthreads();
#pragma unroll
    for (int off = SCAN_TPB / 2; off > 0; off >>= 1) {
        if (t < off) shoff[t] += shoff[t + off];
        __syncthreads();
    }
#pragma unroll
    for (int off = 1; off < SCAN_TPB; off <<= 1) {
        int v = sh[t];
        int add = (t >= off) ? sh[t - off] : 0;
        __syncthreads();
        sh[t] = v + add;
        __syncthreads();
    }
    int excl = sh[t] - c + shoff[0];
    if (i < NN) {
        g_rowptr[i] = excl;
        g_fill[i]   = excl;
    }
    if (i == NN - 1) g_rowptr[NN] = ET;
}

__global__ void scatter_kernel(const void* __restrict__ ei) {
    int j = blockIdx.x * blockDim.x + threadIdx.x;
    if (j >= ET) return;
    int src, dst;
    if (j < EE) {
        src = load_idx(ei, j);
        dst = load_idx(ei, (long long)EE + j);
    } else {
        src = dst = j - EE;
    }
    int pos = atomicAdd(&g_fill[dst], 1);
    g_srcbuf[pos] = src;
}

// ---------------- GEMM: g_h = in @ W  (8 nodes/block, 96 threads, f32x2) ----------------
// Also resets the global es-max accumulator for the following esed pass.
template <int IN>
__global__ void gemm_kernel(const float* __restrict__ x, int in_sel,
                            const float* __restrict__ W) {
    __shared__ __align__(16) float2 xs[IN][4];   // [k][pair]; pair p = nodes (2p, 2p+1)
    if (blockIdx.x == 0 && threadIdx.x == 0) g_esmax_u = fenc(-1e30f);
    const float* in = (in_sel == 0) ? x : sel_buf(in_sel);
    int nb = blockIdx.x * 8;
    int o  = threadIdx.x;   // 0..95
    for (int idx = o; idx < 8 * IN; idx += HID) {
        int n = idx / IN, c = idx % IN;
        ((float*)&xs[c][n >> 1])[n & 1] = in[(nb + n) * IN + c];
    }
    __syncthreads();

    unsigned long long acc0 = 0ull, acc1 = 0ull, acc2 = 0ull, acc3 = 0ull;
#pragma unroll 8
    for (int k = 0; k < IN; k++) {
        float w = W[k * HID + o];
        unsigned long long ww;
        asm("mov.b64 %0, {%1, %1};" : "=l"(ww) : "r"(__float_as_uint(w)));
        ulonglong2 X01 = *reinterpret_cast<const ulonglong2*>(&xs[k][0]);
        ulonglong2 X23 = *reinterpret_cast<const ulonglong2*>(&xs[k][2]);
        asm("fma.rn.f32x2 %0, %1, %2, %0;" : "+l"(acc0) : "l"(X01.x), "l"(ww));
        asm("fma.rn.f32x2 %0, %1, %2, %0;" : "+l"(acc1) : "l"(X01.y), "l"(ww));
        asm("fma.rn.f32x2 %0, %1, %2, %0;" : "+l"(acc2) : "l"(X23.x), "l"(ww));
        asm("fma.rn.f32x2 %0, %1, %2, %0;" : "+l"(acc3) : "l"(X23.y), "l"(ww));
    }

    g_h[(nb + 0) * HID + o] = __uint_as_float((unsigned)acc0);
    g_h[(nb + 1) * HID + o] = __uint_as_float((unsigned)(acc0 >> 32));
    g_h[(nb + 2) * HID + o] = __uint_as_float((unsigned)acc1);
    g_h[(nb + 3) * HID + o] = __uint_as_float((unsigned)(acc1 >> 32));
    g_h[(nb + 4) * HID + o] = __uint_as_float((unsigned)acc2);
    g_h[(nb + 5) * HID + o] = __uint_as_float((unsigned)(acc2 >> 32));
    g_h[(nb + 6) * HID + o] = __uint_as_float((unsigned)acc3);
    g_h[(nb + 7) * HID + o] = __uint_as_float((unsigned)(acc3 >> 32));
}

// ---------------- per-node attention logits + global max(es) ----------------
// Blocks are full (NN*32/256 = 6250 exact). One atomicMax per block.
__global__ void esed_kernel(const float* __restrict__ as, const float* __restrict__ ad) {
    __shared__ float smax[8];
    int node = (blockIdx.x * blockDim.x + threadIdx.x) >> 5;
    int lane = threadIdx.x & 31;
    int wid  = threadIdx.x >> 5;
    float vs = 0.f, vd = 0.f;
    if (lane < 24) {
        float4 hv = ((const float4*)(g_h + node * HID))[lane];
        float4 a4 = ((const float4*)as)[lane];
        float4 d4 = ((const float4*)ad)[lane];
        vs = hv.x * a4.x + hv.y * a4.y + hv.z * a4.z + hv.w * a4.w;
        vd = hv.x * d4.x + hv.y * d4.y + hv.z * d4.z + hv.w * d4.w;
    }
#pragma unroll
    for (int off = 16; off; off >>= 1) {
        vs += __shfl_xor_sync(0xFFFFFFFFu, vs, off);
        vd += __shfl_xor_sync(0xFFFFFFFFu, vd, off);
    }
    if (lane == 0) {
        g_es[node] = vs;
        g_ed[node] = vd;
        smax[wid] = vs;
    }
    __syncthreads();
    if (threadIdx.x == 0) {
        float m = smax[0];
#pragma unroll
        for (int i = 1; i < 8; i++) m = fmaxf(m, smax[i]);
        atomicMax(&g_esmax_u, fenc(m));
    }
}

// ---------------- aggregation: one warp per destination node (R10 form, no max pass) ----------------
// Softmax shift c = lrelu(ESmax + ed[node]) >= every logit of this node
// (ESmax >= es[s] for all s; leakyrelu monotone). Shift cancels exactly in
// alpha = ex / sum(ex) -> bitwise-stable softmax, one less gather pass.
template <bool RESID, bool FINAL>
__global__ void agg_kernel(const float* __restrict__ b, int resid_sel, int out_sel,
                           const float* __restrict__ Wf,
                           const float* __restrict__ asf,
                           const float* __restrict__ adf) {
    int node = (blockIdx.x * blockDim.x + threadIdx.x) >> 5;
    int lane = threadIdx.x & 31;
    if (node >= NN) return;
    int beg = g_rowptr[node], end = g_rowptr[node + 1];
    float edst = g_ed[node];
    float m = fdec(g_esmax_u) + edst;
    m = (m > 0.f) ? m : NEG * m;

    float a0 = 0.f, a1 = 0.f, a2 = 0.f, ssum = 0.f;
#pragma unroll 4
    for (int j = beg; j < end; j++) {
        int s = g_srcbuf[j];                 // broadcast load
        float e = g_es[s] + edst;            // broadcast load
        e = (e > 0.f) ? e : NEG * e;
        float ex = __expf(e - m);
        const float* hp = g_h + s * HID;
        ssum += ex;
        a0 += ex * hp[lane];
        a1 += ex * hp[lane + 32];
        a2 += ex * hp[lane + 64];
    }
    float inv = 1.f / ssum;
    float o0 = a0 * inv + b[lane];
    float o1 = a1 * inv + b[lane + 32];
    float o2 = a2 * inv + b[lane + 64];
    if (RESID) {
        const float* rp = sel_buf(resid_sel) + node * HID;
        o0 += rp[lane]; o1 += rp[lane + 32]; o2 += rp[lane + 64];
    }
    o0 = fmaxf(o0, 0.f); o1 = fmaxf(o1, 0.f); o2 = fmaxf(o2, 0.f);
    if (FINAL) {
        float v = o0 * Wf[lane] + o1 * Wf[lane + 32] + o2 * Wf[lane + 64];
#pragma unroll
        for (int off = 16; off; off >>= 1)
            v += __shfl_xor_sync(0xFFFFFFFFu, v, off);
        if (lane == 0) {
            g_hf[node]  = v;
            g_esf[node] = v * asf[0];
            g_edf[node] = v * adf[0];
        }
    } else {
        float* op = sel_buf(out_sel) + node * HID;
        op[lane] = o0; op[lane + 32] = o1; op[lane + 64] = o2;
    }
}

// ---------------- final aggregation (out dim = 1) ----------------
__global__ void fagg_kernel(const float* __restrict__ bf, float* __restrict__ out) {
    int node = (blockIdx.x * blockDim.x + threadIdx.x) >> 5;
    int lane = threadIdx.x & 31;
    if (node >= NN) return;
    int beg = g_rowptr[node], end = g_rowptr[node + 1];
    float edst = g_edf[node];

    float m = -1e30f;
    for (int j = beg + lane; j < end; j += 32) {
        float e = g_esf[g_srcbuf[j]] + edst;
        e = (e > 0.f) ? e : NEG * e;
        m = fmaxf(m, e);
    }
#pragma unroll
    for (int off = 16; off; off >>= 1)
        m = fmaxf(m, __shfl_xor_sync(0xFFFFFFFFu, m, off));

    float ssum = 0.f, wsum = 0.f;
    for (int j = beg + lane; j < end; j += 32) {
        int s = g_srcbuf[j];
        float e = g_esf[s] + edst;
        e = (e > 0.f) ? e : NEG * e;
        float ex = __expf(e - m);
        ssum += ex;
        wsum += ex * g_hf[s];
    }
#pragma unroll
    for (int off = 16; off; off >>= 1) {
        ssum += __shfl_xor_sync(0xFFFFFFFFu, ssum, off);
        wsum += __shfl_xor_sync(0xFFFFFFFFu, wsum, off);
    }
    if (lane == 0) out[node] = wsum / ssum + bf[0];
}

// ---------------- launch ----------------
extern "C" void kernel_launch(void* const* d_in, const int* in_sizes, int n_in,
                              void* d_out, int out_size) {
    const float* x   = (const float*)d_in[0];
    const void*  ei  = d_in[1];
    const float* W0  = (const float*)d_in[3];
    const float* as0 = (const float*)d_in[4];
    const float* ad0 = (const float*)d_in[5];
    const float* b0  = (const float*)d_in[6];
    const float* W1  = (const float*)d_in[7];
    const float* as1 = (const float*)d_in[8];
    const float* ad1 = (const float*)d_in[9];
    const float* b1  = (const float*)d_in[10];
    const float* W2  = (const float*)d_in[11];
    const float* as2 = (const float*)d_in[12];
    const float* ad2 = (const float*)d_in[13];
    const float* b2  = (const float*)d_in[14];
    const float* Wf  = (const float*)d_in[15];
    const float* asf = (const float*)d_in[16];
    const float* adf = (const float*)d_in[17];
    const float* bf  = (const float*)d_in[18];
    float* out = (float*)d_out;

    const int TPB = 256;
    const int edge_blocks = (ET + TPB - 1) / TPB;
    const int node_warp_blocks = (NN * 32 + TPB - 1) / TPB;   // 1 warp per node

    // CSR build (sort edges by dst, include self loops)
    init_kernel<<<SCAN_BLOCKS, SCAN_TPB>>>((const int*)ei);
    hist_kernel<<<edge_blocks, TPB>>>(ei);
    bsum_kernel<<<SCAN_BLOCKS, SCAN_TPB>>>();
    scanout_kernel<<<SCAN_BLOCKS, SCAN_TPB>>>();
    scatter_kernel<<<edge_blocks, TPB>>>(ei);

    // Layer 0: 32 -> 96, no residual, relu.  out -> bufA
    gemm_kernel<32><<<NN / 8, HID>>>(x, 0, W0);
    esed_kernel<<<node_warp_blocks, TPB>>>(as0, ad0);
    agg_kernel<false, false><<<node_warp_blocks, TPB>>>(b0, 0, 1, nullptr, nullptr, nullptr);

    // Layer 1: 96 -> 96, residual(bufA), relu.  out -> bufB
    gemm_kernel<HID><<<NN / 8, HID>>>(nullptr, 1, W1);
    esed_kernel<<<node_warp_blocks, TPB>>>(as1, ad1);
    agg_kernel<true, false><<<node_warp_blocks, TPB>>>(b1, 1, 2, nullptr, nullptr, nullptr);

    // Layer 2: 96 -> 96, residual(bufB), relu, fused final 96->1 projection
    gemm_kernel<HID><<<NN / 8, HID>>>(nullptr, 2, W2);
    esed_kernel<<<node_warp_blocks, TPB>>>(as2, ad2);
    agg_kernel<true, true><<<node_warp_blocks, TPB>>>(b2, 2, 0, Wf, asf, adf);

    // Final layer aggregation (dim 1)
    fagg_kernel<<<node_warp_blocks, TPB>>>(bf, out);
}

// round 13
// speedup vs baseline: 1.0842x; 1.0345x over previous
#include <cuda_runtime.h>

#define NN 50000
#define EE 800000
#define ET 850000   // EE + NN self loops
#define HID 96
#define NEG 0.2f

#define SCAN_TPB 256
#define SCAN_BLOCKS ((NN + SCAN_TPB - 1) / SCAN_TPB)   // 196

// ---------------- scratch (no cudaMalloc allowed) ----------------
__device__ float g_h[NN * HID];
__device__ float g_bufA[NN * HID];
__device__ float g_bufB[NN * HID];
__device__ float g_es[NN];
__device__ float g_ed[NN];
__device__ float g_hf[NN];
__device__ float g_esf[NN];
__device__ float g_edf[NN];
__device__ unsigned g_max_u[4];     // ordered-float max: slots 0-2 = es per layer, 3 = esf
__device__ int   g_cnt[NN];
__device__ int   g_rowptr[NN + 1];
__device__ int   g_fill[NN];
__device__ int   g_srcbuf[ET];
__device__ int   g_bsum[SCAN_BLOCKS];
__device__ int   g_is64;

__device__ __forceinline__ float* sel_buf(int s) {
    return (s == 1) ? g_bufA : g_bufB;
}

// order-preserving float <-> uint encoding (for atomicMax on floats)
__device__ __forceinline__ unsigned fenc(float f) {
    unsigned u = __float_as_uint(f);
    return (u & 0x80000000u) ? ~u : (u | 0x80000000u);
}
__device__ __forceinline__ float fdec(unsigned e) {
    unsigned u = (e & 0x80000000u) ? (e & 0x7FFFFFFFu) : ~e;
    return __uint_as_float(u);
}

// ---------------- init: zero counters + max slots + dtype probe ----------------
// edge_index dtype: reference asks int64 but JAX without x64 emits int32.
__global__ void init_kernel(const int* __restrict__ ei32) {
    int i = blockIdx.x * blockDim.x + threadIdx.x;
    if (i < NN) g_cnt[i] = 0;
    if (i < 4) g_max_u[i] = fenc(-1e30f);
    if (blockIdx.x == 0) {
        __shared__ int nz;
        if (threadIdx.x == 0) nz = 0;
        __syncthreads();
        if (ei32[2 * threadIdx.x + 1] != 0) nz = 1;  // benign race
        __syncthreads();
        if (threadIdx.x == 0) g_is64 = (nz == 0) ? 1 : 0;
    }
}

__device__ __forceinline__ int load_idx(const void* ei, long long pos) {
    if (g_is64) return (int)((const long long*)ei)[pos];
    return ((const int*)ei)[pos];
}

// ---------------- CSR build ----------------
__global__ void hist_kernel(const void* __restrict__ ei) {
    int j = blockIdx.x * blockDim.x + threadIdx.x;
    if (j >= ET) return;
    int dst = (j < EE) ? load_idx(ei, (long long)EE + j) : (j - EE);
    atomicAdd(&g_cnt[dst], 1);
}

__global__ void bsum_kernel() {
    __shared__ int sh[SCAN_TPB];
    int t = threadIdx.x;
    int i = blockIdx.x * SCAN_TPB + t;
    sh[t] = (i < NN) ? g_cnt[i] : 0;
    __syncthreads();
#pragma unroll
    for (int off = SCAN_TPB / 2; off > 0; off >>= 1) {
        if (t < off) sh[t] += sh[t + off];
        __syncthreads();
    }
    if (t == 0) g_bsum[blockIdx.x] = sh[0];
}

__global__ void scanout_kernel() {
    __shared__ int shoff[SCAN_TPB];
    __shared__ int sh[SCAN_TPB];
    int t = threadIdx.x;
    shoff[t] = (t < blockIdx.x && t < SCAN_BLOCKS) ? g_bsum[t] : 0;
    int i = blockIdx.x * SCAN_TPB + t;
    int c = (i < NN) ? g_cnt[i] : 0;
    sh[t] = c;
    __syncthreads();
#pragma unroll
    for (int off = SCAN_TPB / 2; off > 0; off >>= 1) {
        if (t < off) shoff[t] += shoff[t + off];
        __syncthreads();
    }
#pragma unroll
    for (int off = 1; off < SCAN_TPB; off <<= 1) {
        int v = sh[t];
        int add = (t >= off) ? sh[t - off] : 0;
        __syncthreads();
        sh[t] = v + add;
        __syncthreads();
    }
    int excl = sh[t] - c + shoff[0];
    if (i < NN) {
        g_rowptr[i] = excl;
        g_fill[i]   = excl;
    }
    if (i == NN - 1) g_rowptr[NN] = ET;
}

__global__ void scatter_kernel(const void* __restrict__ ei) {
    int j = blockIdx.x * blockDim.x + threadIdx.x;
    if (j >= ET) return;
    int src, dst;
    if (j < EE) {
        src = load_idx(ei, j);
        dst = load_idx(ei, (long long)EE + j);
    } else {
        src = dst = j - EE;
    }
    int pos = atomicAdd(&g_fill[dst], 1);
    g_srcbuf[pos] = src;
}

// ---------------- GEMM + fused es/ed: 8 nodes/block, 96 threads, f32x2 ----------------
// After the mainloop h lives in registers; it is staged to smem and the 3 warps
// compute es/ed per node (same float4+shfl order as the old esed kernel) plus
// one atomicMax per block into g_max_u[slot].
template <int IN>
__global__ void gemm_kernel(const float* __restrict__ x, int in_sel,
                            const float* __restrict__ W,
                            const float* __restrict__ as, const float* __restrict__ ad,
                            int slot) {
    __shared__ __align__(16) float2 xs[IN][4];   // [k][pair]; pair p = nodes (2p, 2p+1)
    __shared__ __align__(16) float sh_h[8][HID];
    __shared__ float sred[3];
    const float* in = (in_sel == 0) ? x : sel_buf(in_sel);
    int nb = blockIdx.x * 8;
    int o  = threadIdx.x;   // 0..95
    int lane = o & 31, wid = o >> 5;
    for (int idx = o; idx < 8 * IN; idx += HID) {
        int n = idx / IN, c = idx % IN;
        ((float*)&xs[c][n >> 1])[n & 1] = in[(nb + n) * IN + c];
    }
    __syncthreads();

    unsigned long long acc0 = 0ull, acc1 = 0ull, acc2 = 0ull, acc3 = 0ull;
#pragma unroll 8
    for (int k = 0; k < IN; k++) {
        float w = W[k * HID + o];
        unsigned long long ww;
        asm("mov.b64 %0, {%1, %1};" : "=l"(ww) : "r"(__float_as_uint(w)));
        ulonglong2 X01 = *reinterpret_cast<const ulonglong2*>(&xs[k][0]);
        ulonglong2 X23 = *reinterpret_cast<const ulonglong2*>(&xs[k][2]);
        asm("fma.rn.f32x2 %0, %1, %2, %0;" : "+l"(acc0) : "l"(X01.x), "l"(ww));
        asm("fma.rn.f32x2 %0, %1, %2, %0;" : "+l"(acc1) : "l"(X01.y), "l"(ww));
        asm("fma.rn.f32x2 %0, %1, %2, %0;" : "+l"(acc2) : "l"(X23.x), "l"(ww));
        asm("fma.rn.f32x2 %0, %1, %2, %0;" : "+l"(acc3) : "l"(X23.y), "l"(ww));
    }

    float h0 = __uint_as_float((unsigned)acc0);
    float h1 = __uint_as_float((unsigned)(acc0 >> 32));
    float h2 = __uint_as_float((unsigned)acc1);
    float h3 = __uint_as_float((unsigned)(acc1 >> 32));
    float h4 = __uint_as_float((unsigned)acc2);
    float h5 = __uint_as_float((unsigned)(acc2 >> 32));
    float h6 = __uint_as_float((unsigned)acc3);
    float h7 = __uint_as_float((unsigned)(acc3 >> 32));
    g_h[(nb + 0) * HID + o] = h0;  sh_h[0][o] = h0;
    g_h[(nb + 1) * HID + o] = h1;  sh_h[1][o] = h1;
    g_h[(nb + 2) * HID + o] = h2;  sh_h[2][o] = h2;
    g_h[(nb + 3) * HID + o] = h3;  sh_h[3][o] = h3;
    g_h[(nb + 4) * HID + o] = h4;  sh_h[4][o] = h4;
    g_h[(nb + 5) * HID + o] = h5;  sh_h[5][o] = h5;
    g_h[(nb + 6) * HID + o] = h6;  sh_h[6][o] = h6;
    g_h[(nb + 7) * HID + o] = h7;  sh_h[7][o] = h7;
    __syncthreads();

    // fused es/ed (warp wid handles nodes wid, wid+3, wid+6)
    float4 a4 = make_float4(0.f, 0.f, 0.f, 0.f), d4 = a4;
    if (lane < 24) {
        a4 = ((const float4*)as)[lane];
        d4 = ((const float4*)ad)[lane];
    }
    float wmax = -1e30f;
    for (int n = wid; n < 8; n += 3) {
        float vs = 0.f, vd = 0.f;
        if (lane < 24) {
            float4 hv = *(const float4*)&sh_h[n][lane * 4];
            vs = hv.x * a4.x + hv.y * a4.y + hv.z * a4.z + hv.w * a4.w;
            vd = hv.x * d4.x + hv.y * d4.y + hv.z * d4.z + hv.w * d4.w;
        }
#pragma unroll
        for (int off = 16; off; off >>= 1) {
            vs += __shfl_xor_sync(0xFFFFFFFFu, vs, off);
            vd += __shfl_xor_sync(0xFFFFFFFFu, vd, off);
        }
        if (lane == 0) {
            g_es[nb + n] = vs;
            g_ed[nb + n] = vd;
            wmax = fmaxf(wmax, vs);
        }
    }
    if (lane == 0) sred[wid] = wmax;
    __syncthreads();
    if (o == 0)
        atomicMax(&g_max_u[slot], fenc(fmaxf(fmaxf(sred[0], sred[1]), sred[2])));
}

// ---------------- aggregation: one warp per destination node (no max pass) ----------------
// Softmax shift c = lrelu(ESmax + ed[node]) >= every logit of this node.
// FINAL additionally block-maxes esf into g_max_u[3] for fagg's shift.
// Grids are exact (6250 blocks * 8 warps = NN), so no early returns.
template <bool RESID, bool FINAL>
__global__ void agg_kernel(const float* __restrict__ b, int resid_sel, int out_sel,
                           int slot,
                           const float* __restrict__ Wf,
                           const float* __restrict__ asf,
                           const float* __restrict__ adf) {
    int node = (blockIdx.x * blockDim.x + threadIdx.x) >> 5;
    int lane = threadIdx.x & 31;
    int beg = g_rowptr[node], end = g_rowptr[node + 1];
    float edst = g_ed[node];
    float m = fdec(g_max_u[slot]) + edst;
    m = (m > 0.f) ? m : NEG * m;

    float a0 = 0.f, a1 = 0.f, a2 = 0.f, ssum = 0.f;
#pragma unroll 4
    for (int j = beg; j < end; j++) {
        int s = g_srcbuf[j];                 // broadcast load
        float e = g_es[s] + edst;            // broadcast load
        e = (e > 0.f) ? e : NEG * e;
        float ex = __expf(e - m);
        const float* hp = g_h + s * HID;
        ssum += ex;
        a0 += ex * hp[lane];
        a1 += ex * hp[lane + 32];
        a2 += ex * hp[lane + 64];
    }
    float inv = 1.f / ssum;
    float o0 = a0 * inv + b[lane];
    float o1 = a1 * inv + b[lane + 32];
    float o2 = a2 * inv + b[lane + 64];
    if (RESID) {
        const float* rp = sel_buf(resid_sel) + node * HID;
        o0 += rp[lane]; o1 += rp[lane + 32]; o2 += rp[lane + 64];
    }
    o0 = fmaxf(o0, 0.f); o1 = fmaxf(o1, 0.f); o2 = fmaxf(o2, 0.f);
    if (FINAL) {
        __shared__ float smaxf[8];
        float v = o0 * Wf[lane] + o1 * Wf[lane + 32] + o2 * Wf[lane + 64];
#pragma unroll
        for (int off = 16; off; off >>= 1)
            v += __shfl_xor_sync(0xFFFFFFFFu, v, off);
        float esf = v * asf[0];
        if (lane == 0) {
            g_hf[node]  = v;
            g_esf[node] = esf;
            g_edf[node] = v * adf[0];
            smaxf[threadIdx.x >> 5] = esf;
        }
        __syncthreads();
        if (threadIdx.x == 0) {
            float mm = smaxf[0];
#pragma unroll
            for (int i = 1; i < 8; i++) mm = fmaxf(mm, smaxf[i]);
            atomicMax(&g_max_u[3], fenc(mm));
        }
    } else {
        float* op = sel_buf(out_sel) + node * HID;
        op[lane] = o0; op[lane + 32] = o1; op[lane + 64] = o2;
    }
}

// ---------------- final aggregation (out dim = 1, no max pass) ----------------
__global__ void fagg_kernel(const float* __restrict__ bf, float* __restrict__ out) {
    int node = (blockIdx.x * blockDim.x + threadIdx.x) >> 5;
    int lane = threadIdx.x & 31;
    if (node >= NN) return;
    int beg = g_rowptr[node], end = g_rowptr[node + 1];
    float edst = g_edf[node];
    float m = fdec(g_max_u[3]) + edst;
    m = (m > 0.f) ? m : NEG * m;

    float ssum = 0.f, wsum = 0.f;
    for (int j = beg + lane; j < end; j += 32) {
        int s = g_srcbuf[j];
        float e = g_esf[s] + edst;
        e = (e > 0.f) ? e : NEG * e;
        float ex = __expf(e - m);
        ssum += ex;
        wsum += ex * g_hf[s];
    }
#pragma unroll
    for (int off = 16; off; off >>= 1) {
        ssum += __shfl_xor_sync(0xFFFFFFFFu, ssum, off);
        wsum += __shfl_xor_sync(0xFFFFFFFFu, wsum, off);
    }
    if (lane == 0) out[node] = wsum / ssum + bf[0];
}

// ---------------- launch ----------------
extern "C" void kernel_launch(void* const* d_in, const int* in_sizes, int n_in,
                              void* d_out, int out_size) {
    const float* x   = (const float*)d_in[0];
    const void*  ei  = d_in[1];
    const float* W0  = (const float*)d_in[3];
    const float* as0 = (const float*)d_in[4];
    const float* ad0 = (const float*)d_in[5];
    const float* b0  = (const float*)d_in[6];
    const float* W1  = (const float*)d_in[7];
    const float* as1 = (const float*)d_in[8];
    const float* ad1 = (const float*)d_in[9];
    const float* b1  = (const float*)d_in[10];
    const float* W2  = (const float*)d_in[11];
    const float* as2 = (const float*)d_in[12];
    const float* ad2 = (const float*)d_in[13];
    const float* b2  = (const float*)d_in[14];
    const float* Wf  = (const float*)d_in[15];
    const float* asf = (const float*)d_in[16];
    const float* adf = (const float*)d_in[17];
    const float* bf  = (const float*)d_in[18];
    float* out = (float*)d_out;

    const int TPB = 256;
    const int edge_blocks = (ET + TPB - 1) / TPB;
    const int node_warp_blocks = (NN * 32 + TPB - 1) / TPB;   // 6250, exact

    // CSR build (sort edges by dst, include self loops)
    init_kernel<<<SCAN_BLOCKS, SCAN_TPB>>>((const int*)ei);
    hist_kernel<<<edge_blocks, TPB>>>(ei);
    bsum_kernel<<<SCAN_BLOCKS, SCAN_TPB>>>();
    scanout_kernel<<<SCAN_BLOCKS, SCAN_TPB>>>();
    scatter_kernel<<<edge_blocks, TPB>>>(ei);

    // Layer 0: 32 -> 96, no residual, relu.  out -> bufA
    gemm_kernel<32><<<NN / 8, HID>>>(x, 0, W0, as0, ad0, 0);
    agg_kernel<false, false><<<node_warp_blocks, TPB>>>(b0, 0, 1, 0, nullptr, nullptr, nullptr);

    // Layer 1: 96 -> 96, residual(bufA), relu.  out -> bufB
    gemm_kernel<HID><<<NN / 8, HID>>>(nullptr, 1, W1, as1, ad1, 1);
    agg_kernel<true, false><<<node_warp_blocks, TPB>>>(b1, 1, 2, 1, nullptr, nullptr, nullptr);

    // Layer 2: 96 -> 96, residual(bufB), relu, fused final 96->1 projection
    gemm_kernel<HID><<<NN / 8, HID>>>(nullptr, 2, W2, as2, ad2, 2);
    agg_kernel<true, true><<<node_warp_blocks, TPB>>>(b2, 2, 0, 2, Wf, asf, adf);

    // Final layer aggregation (dim 1)
    fagg_kernel<<<node_warp_blocks, TPB>>>(bf, out);
}

// round 14
// speedup vs baseline: 1.1048x; 1.0190x over previous
#include <cuda_runtime.h>

#define NN 50000
#define EE 800000
#define ET 850000   // EE + NN self loops
#define HID 96
#define NEG 0.2f

#define SCAN_TPB 256
#define SCAN_BLOCKS ((NN + SCAN_TPB - 1) / SCAN_TPB)   // 196

// ---------------- scratch (no cudaMalloc allowed) ----------------
__device__ float g_h[NN * HID];
__device__ float g_bufA[NN * HID];
__device__ float g_bufB[NN * HID];
__device__ float g_es[NN];
__device__ float g_ed[NN];
__device__ float2 g_hesf[NN];       // (hf, esf) packed for fagg
__device__ float g_edf[NN];
__device__ unsigned g_max_u[4];     // ordered-float max: slots 0-2 = es per layer, 3 = esf
__device__ int   g_cnt[NN];         // ALWAYS zero at launch entry (module init + scanout self-clean)
__device__ int   g_rowptr[NN + 1];
__device__ int   g_fill[NN];
__device__ int   g_srcbuf[ET];
__device__ int   g_bsum[SCAN_BLOCKS];
__device__ int   g_is64;

__device__ __forceinline__ float* sel_buf(int s) {
    return (s == 1) ? g_bufA : g_bufB;
}

// order-preserving float <-> uint encoding (for atomicMax on floats)
__device__ __forceinline__ unsigned fenc(float f) {
    unsigned u = __float_as_uint(f);
    return (u & 0x80000000u) ? ~u : (u | 0x80000000u);
}
__device__ __forceinline__ float fdec(unsigned e) {
    unsigned u = (e & 0x80000000u) ? (e & 0x7FFFFFFFu) : ~e;
    return __uint_as_float(u);
}

// ---------------- reset: dtype probe + max slots (1 block; must precede gemm0) ----------------
__global__ void rst_kernel(const int* __restrict__ ei32) {
    __shared__ int nz;
    if (threadIdx.x == 0) nz = 0;
    __syncthreads();
    if (ei32[2 * threadIdx.x + 1] != 0) nz = 1;  // benign race
    __syncthreads();
    if (threadIdx.x == 0) g_is64 = (nz == 0) ? 1 : 0;
    if (threadIdx.x < 4) g_max_u[threadIdx.x] = fenc(-1e30f);
}

__device__ __forceinline__ int load_idx(const void* ei, long long pos) {
    if (g_is64) return (int)((const long long*)ei)[pos];
    return ((const int*)ei)[pos];
}

// ---------------- CSR build ----------------
__global__ void hist_kernel(const void* __restrict__ ei) {
    int j = blockIdx.x * blockDim.x + threadIdx.x;
    if (j >= ET) return;
    int dst = (j < EE) ? load_idx(ei, (long long)EE + j) : (j - EE);
    atomicAdd(&g_cnt[dst], 1);
}

__global__ void bsum_kernel() {
    __shared__ int sh[SCAN_TPB];
    int t = threadIdx.x;
    int i = blockIdx.x * SCAN_TPB + t;
    sh[t] = (i < NN) ? g_cnt[i] : 0;
    __syncthreads();
#pragma unroll
    for (int off = SCAN_TPB / 2; off > 0; off >>= 1) {
        if (t < off) sh[t] += sh[t + off];
        __syncthreads();
    }
    if (t == 0) g_bsum[blockIdx.x] = sh[0];
}

__global__ void scanout_kernel() {
    __shared__ int shoff[SCAN_TPB];
    __shared__ int sh[SCAN_TPB];
    int t = threadIdx.x;
    shoff[t] = (t < blockIdx.x && t < SCAN_BLOCKS) ? g_bsum[t] : 0;
    int i = blockIdx.x * SCAN_TPB + t;
    int c = (i < NN) ? g_cnt[i] : 0;
    if (i < NN) g_cnt[i] = 0;   // self-clean: keeps the "g_cnt==0 at entry" invariant
    sh[t] = c;
    __syncthreads();
#pragma unroll
    for (int off = SCAN_TPB / 2; off > 0; off >>= 1) {
        if (t < off) shoff[t] += shoff[t + off];
        __syncthreads();
    }
#pragma unroll
    for (int off = 1; off < SCAN_TPB; off <<= 1) {
        int v = sh[t];
        int add = (t >= off) ? sh[t - off] : 0;
        __syncthreads();
        sh[t] = v + add;
        __syncthreads();
    }
    int excl = sh[t] - c + shoff[0];
    if (i < NN) {
        g_rowptr[i] = excl;
        g_fill[i]   = excl;
    }
    if (i == NN - 1) g_rowptr[NN] = ET;
}

__global__ void scatter_kernel(const void* __restrict__ ei) {
    int j = blockIdx.x * blockDim.x + threadIdx.x;
    if (j >= ET) return;
    int src, dst;
    if (j < EE) {
        src = load_idx(ei, j);
        dst = load_idx(ei, (long long)EE + j);
    } else {
        src = dst = j - EE;
    }
    int pos = atomicAdd(&g_fill[dst], 1);
    g_srcbuf[pos] = src;
}

// ---------------- GEMM + fused es/ed: 8 nodes/block, 96 threads, f32x2 ----------------
template <int IN>
__global__ void gemm_kernel(const float* __restrict__ x, int in_sel,
                            const float* __restrict__ W,
                            const float* __restrict__ as, const float* __restrict__ ad,
                            int slot) {
    __shared__ __align__(16) float2 xs[IN][4];   // [k][pair]; pair p = nodes (2p, 2p+1)
    __shared__ __align__(16) float sh_h[8][HID];
    __shared__ float sred[3];
    const float* in = (in_sel == 0) ? x : sel_buf(in_sel);
    int nb = blockIdx.x * 8;
    int o  = threadIdx.x;   // 0..95
    int lane = o & 31, wid = o >> 5;
    for (int idx = o; idx < 8 * IN; idx += HID) {
        int n = idx / IN, c = idx % IN;
        ((float*)&xs[c][n >> 1])[n & 1] = in[(nb + n) * IN + c];
    }
    __syncthreads();

    unsigned long long acc0 = 0ull, acc1 = 0ull, acc2 = 0ull, acc3 = 0ull;
#pragma unroll 8
    for (int k = 0; k < IN; k++) {
        float w = W[k * HID + o];
        unsigned long long ww;
        asm("mov.b64 %0, {%1, %1};" : "=l"(ww) : "r"(__float_as_uint(w)));
        ulonglong2 X01 = *reinterpret_cast<const ulonglong2*>(&xs[k][0]);
        ulonglong2 X23 = *reinterpret_cast<const ulonglong2*>(&xs[k][2]);
        asm("fma.rn.f32x2 %0, %1, %2, %0;" : "+l"(acc0) : "l"(X01.x), "l"(ww));
        asm("fma.rn.f32x2 %0, %1, %2, %0;" : "+l"(acc1) : "l"(X01.y), "l"(ww));
        asm("fma.rn.f32x2 %0, %1, %2, %0;" : "+l"(acc2) : "l"(X23.x), "l"(ww));
        asm("fma.rn.f32x2 %0, %1, %2, %0;" : "+l"(acc3) : "l"(X23.y), "l"(ww));
    }

    float h0 = __uint_as_float((unsigned)acc0);
    float h1 = __uint_as_float((unsigned)(acc0 >> 32));
    float h2 = __uint_as_float((unsigned)acc1);
    float h3 = __uint_as_float((unsigned)(acc1 >> 32));
    float h4 = __uint_as_float((unsigned)acc2);
    float h5 = __uint_as_float((unsigned)(acc2 >> 32));
    float h6 = __uint_as_float((unsigned)acc3);
    float h7 = __uint_as_float((unsigned)(acc3 >> 32));
    g_h[(nb + 0) * HID + o] = h0;  sh_h[0][o] = h0;
    g_h[(nb + 1) * HID + o] = h1;  sh_h[1][o] = h1;
    g_h[(nb + 2) * HID + o] = h2;  sh_h[2][o] = h2;
    g_h[(nb + 3) * HID + o] = h3;  sh_h[3][o] = h3;
    g_h[(nb + 4) * HID + o] = h4;  sh_h[4][o] = h4;
    g_h[(nb + 5) * HID + o] = h5;  sh_h[5][o] = h5;
    g_h[(nb + 6) * HID + o] = h6;  sh_h[6][o] = h6;
    g_h[(nb + 7) * HID + o] = h7;  sh_h[7][o] = h7;
    __syncthreads();

    // fused es/ed (warp wid handles nodes wid, wid+3, wid+6)
    float4 a4 = make_float4(0.f, 0.f, 0.f, 0.f), d4 = a4;
    if (lane < 24) {
        a4 = ((const float4*)as)[lane];
        d4 = ((const float4*)ad)[lane];
    }
    float wmax = -1e30f;
    for (int n = wid; n < 8; n += 3) {
        float vs = 0.f, vd = 0.f;
        if (lane < 24) {
            float4 hv = *(const float4*)&sh_h[n][lane * 4];
            vs = hv.x * a4.x + hv.y * a4.y + hv.z * a4.z + hv.w * a4.w;
            vd = hv.x * d4.x + hv.y * d4.y + hv.z * d4.z + hv.w * d4.w;
        }
#pragma unroll
        for (int off = 16; off; off >>= 1) {
            vs += __shfl_xor_sync(0xFFFFFFFFu, vs, off);
            vd += __shfl_xor_sync(0xFFFFFFFFu, vd, off);
        }
        if (lane == 0) {
            g_es[nb + n] = vs;
            g_ed[nb + n] = vd;
            wmax = fmaxf(wmax, vs);
        }
    }
    if (lane == 0) sred[wid] = wmax;
    __syncthreads();
    if (o == 0)
        atomicMax(&g_max_u[slot], fenc(fmaxf(fmaxf(sred[0], sred[1]), sred[2])));
}

// ---------------- aggregation: one warp per destination node (no max pass) ----------------
// Softmax shift c = lrelu(ESmax + ed[node]) >= every logit of this node.
// FINAL block-maxes esf into g_max_u[3] and writes packed (hf, esf).
template <bool RESID, bool FINAL>
__global__ void agg_kernel(const float* __restrict__ b, int resid_sel, int out_sel,
                           int slot,
                           const float* __restrict__ Wf,
                           const float* __restrict__ asf,
                           const float* __restrict__ adf) {
    int node = (blockIdx.x * blockDim.x + threadIdx.x) >> 5;
    int lane = threadIdx.x & 31;
    int beg = g_rowptr[node], end = g_rowptr[node + 1];
    float edst = g_ed[node];
    float m = fdec(g_max_u[slot]) + edst;
    m = (m > 0.f) ? m : NEG * m;

    float a0 = 0.f, a1 = 0.f, a2 = 0.f, ssum = 0.f;
#pragma unroll 4
    for (int j = beg; j < end; j++) {
        int s = g_srcbuf[j];                 // broadcast load
        float e = g_es[s] + edst;            // broadcast load
        e = (e > 0.f) ? e : NEG * e;
        float ex = __expf(e - m);
        const float* hp = g_h + s * HID;
        ssum += ex;
        a0 += ex * hp[lane];
        a1 += ex * hp[lane + 32];
        a2 += ex * hp[lane + 64];
    }
    float inv = 1.f / ssum;
    float o0 = a0 * inv + b[lane];
    float o1 = a1 * inv + b[lane + 32];
    float o2 = a2 * inv + b[lane + 64];
    if (RESID) {
        const float* rp = sel_buf(resid_sel) + node * HID;
        o0 += rp[lane]; o1 += rp[lane + 32]; o2 += rp[lane + 64];
    }
    o0 = fmaxf(o0, 0.f); o1 = fmaxf(o1, 0.f); o2 = fmaxf(o2, 0.f);
    if (FINAL) {
        __shared__ float smaxf[8];
        float v = o0 * Wf[lane] + o1 * Wf[lane + 32] + o2 * Wf[lane + 64];
#pragma unroll
        for (int off = 16; off; off >>= 1)
            v += __shfl_xor_sync(0xFFFFFFFFu, v, off);
        float esf = v * asf[0];
        if (lane == 0) {
            g_hesf[node] = make_float2(v, esf);
            g_edf[node]  = v * adf[0];
            smaxf[threadIdx.x >> 5] = esf;
        }
        __syncthreads();
        if (threadIdx.x == 0) {
            float mm = smaxf[0];
#pragma unroll
            for (int i = 1; i < 8; i++) mm = fmaxf(mm, smaxf[i]);
            atomicMax(&g_max_u[3], fenc(mm));
        }
    } else {
        float* op = sel_buf(out_sel) + node * HID;
        op[lane] = o0; op[lane + 32] = o1; op[lane + 64] = o2;
    }
}

// ---------------- final aggregation (out dim = 1, no max pass, packed gather) ----------------
__global__ void fagg_kernel(const float* __restrict__ bf, float* __restrict__ out) {
    int node = (blockIdx.x * blockDim.x + threadIdx.x) >> 5;
    int lane = threadIdx.x & 31;
    if (node >= NN) return;
    int beg = g_rowptr[node], end = g_rowptr[node + 1];
    float edst = g_edf[node];
    float m = fdec(g_max_u[3]) + edst;
    m = (m > 0.f) ? m : NEG * m;

    float ssum = 0.f, wsum = 0.f;
    for (int j = beg + lane; j < end; j += 32) {
        int s = g_srcbuf[j];
        float2 he = g_hesf[s];               // one LDG.64: (hf, esf)
        float e = he.y + edst;
        e = (e > 0.f) ? e : NEG * e;
        float ex = __expf(e - m);
        ssum += ex;
        wsum += ex * he.x;
    }
#pragma unroll
    for (int off = 16; off; off >>= 1) {
        ssum += __shfl_xor_sync(0xFFFFFFFFu, ssum, off);
        wsum += __shfl_xor_sync(0xFFFFFFFFu, wsum, off);
    }
    if (lane == 0) out[node] = wsum / ssum + bf[0];
}

// ---------------- launch ----------------
extern "C" void kernel_launch(void* const* d_in, const int* in_sizes, int n_in,
                              void* d_out, int out_size) {
    const float* x   = (const float*)d_in[0];
    const void*  ei  = d_in[1];
    const float* W0  = (const float*)d_in[3];
    const float* as0 = (const float*)d_in[4];
    const float* ad0 = (const float*)d_in[5];
    const float* b0  = (const float*)d_in[6];
    const float* W1  = (const float*)d_in[7];
    const float* as1 = (const float*)d_in[8];
    const float* ad1 = (const float*)d_in[9];
    const float* b1  = (const float*)d_in[10];
    const float* W2  = (const float*)d_in[11];
    const float* as2 = (const float*)d_in[12];
    const float* ad2 = (const float*)d_in[13];
    const float* b2  = (const float*)d_in[14];
    const float* Wf  = (const float*)d_in[15];
    const float* asf = (const float*)d_in[16];
    const float* adf = (const float*)d_in[17];
    const float* bf  = (const float*)d_in[18];
    float* out = (float*)d_out;

    // lazily-created side stream + fork/join events (created on the first,
    // non-captured correctness call; reused during capture)
    static cudaStream_t s2 = nullptr;
    static cudaEvent_t ev_fork = nullptr, ev_join = nullptr;
    if (s2 == nullptr) {
        cudaStreamCreateWithFlags(&s2, cudaStreamNonBlocking);
        cudaEventCreateWithFlags(&ev_fork, cudaEventDisableTiming);
        cudaEventCreateWithFlags(&ev_join, cudaEventDisableTiming);
    }

    const int TPB = 256;
    const int edge_blocks = (ET + TPB - 1) / TPB;
    const int node_warp_blocks = (NN * 32 + TPB - 1) / TPB;   // 6250, exact

    // probe + max-slot reset (must precede gemm0's atomicMax AND the CSR chain)
    rst_kernel<<<1, 256>>>((const int*)ei);

    // fork: CSR build on s2, gemm0 concurrently on the capture stream
    cudaEventRecord(ev_fork, 0);
    cudaStreamWaitEvent(s2, ev_fork, 0);
    hist_kernel<<<edge_blocks, TPB, 0, s2>>>(ei);
    bsum_kernel<<<SCAN_BLOCKS, SCAN_TPB, 0, s2>>>();
    scanout_kernel<<<SCAN_BLOCKS, SCAN_TPB, 0, s2>>>();
    scatter_kernel<<<edge_blocks, TPB, 0, s2>>>(ei);
    cudaEventRecord(ev_join, s2);

    gemm_kernel<32><<<NN / 8, HID>>>(x, 0, W0, as0, ad0, 0);   // concurrent with CSR

    // join: agg0 needs both CSR and gemm0
    cudaStreamWaitEvent(0, ev_join, 0);

    // Layer 0: out -> bufA
    agg_kernel<false, false><<<node_warp_blocks, TPB>>>(b0, 0, 1, 0, nullptr, nullptr, nullptr);

    // Layer 1: residual(bufA), out -> bufB
    gemm_kernel<HID><<<NN / 8, HID>>>(nullptr, 1, W1, as1, ad1, 1);
    agg_kernel<true, false><<<node_warp_blocks, TPB>>>(b1, 1, 2, 1, nullptr, nullptr, nullptr);

    // Layer 2: residual(bufB), fused final 96->1 projection
    gemm_kernel<HID><<<NN / 8, HID>>>(nullptr, 2, W2, as2, ad2, 2);
    agg_kernel<true, true><<<node_warp_blocks, TPB>>>(b2, 2, 0, 2, Wf, asf, adf);

    // Final layer aggregation (dim 1)
    fagg_kernel<<<node_warp_blocks, TPB>>>(bf, out);
}